// round 5
// baseline (speedup 1.0000x reference)
#include <cuda_runtime.h>
#include <cstdint>

// OnlineEmbedding: out[r, :] = table[ids[r], :]
//   ids:   [819200] int32, values in [0, 1e6)
//   table: [1e6, 64] float32 (row = 256 B = 8 x 32B)
//   out:   [819200, 64] float32
//
// R4 fix: L2::evict_last requires 256-bit loads on sm_103a -> use v4.b64.
//  - 8 threads per row, each thread loads 32B via LDG.256 evict_last:
//    repeated ids keep their lines in the 126MB L2.
//  - output stores __stcs (evict_first): write stream doesn't evict table.
//  - 4 rows per 8-thread group: one int4 grabs 4 ids, 4 independent
//    256-bit gathers in flight per thread.

static constexpr int ROWS         = 4096 * 200;  // 819200
static constexpr int ROWS_PER_GRP = 4;
static constexpr int THR_PER_ROW  = 8;           // 8 * 32B = 256B row
static constexpr int F4_PER_ROW   = 16;          // float4 per row

struct V32 { unsigned long long a, b, c, d; };   // 32 bytes

__device__ __forceinline__ V32 ldg256_evict_last(const void* p)
{
    V32 v;
    asm volatile("ld.global.nc.L2::evict_last.v4.b64 {%0,%1,%2,%3}, [%4];"
                 : "=l"(v.a), "=l"(v.b), "=l"(v.c), "=l"(v.d)
                 : "l"(p));
    return v;
}

__device__ __forceinline__ void stcs32(float4* p, const V32& v)
{
    float4 lo, hi;
    lo.x = __ull2float_rz(0);  // placeholder, overwritten below via bit moves
    // reinterpret the four 64-bit words as two float4s
    double2* pd = nullptr; (void)pd;
    ulonglong2 w0 = make_ulonglong2(v.a, v.b);
    ulonglong2 w1 = make_ulonglong2(v.c, v.d);
    lo = *reinterpret_cast<float4*>(&w0);
    hi = *reinterpret_cast<float4*>(&w1);
    __stcs(p, lo);
    __stcs(p + 1, hi);
}

__global__ __launch_bounds__(256)
void embed_gather_kernel(const int* __restrict__ ids,
                         const char* __restrict__ table,
                         float4* __restrict__ out)
{
    int gtid = blockIdx.x * blockDim.x + threadIdx.x;
    int grp  = gtid >> 3;            // group of 8 threads
    int lane = gtid & 7;             // 32B chunk index within row
    int row0 = grp * ROWS_PER_GRP;
    if (row0 >= ROWS) return;

    int4 id4 = __ldcs((const int4*)(ids + row0));

    // 4 independent 256-bit gathers with evict_last retention.
    const char* t = table;
    V32 v0 = ldg256_evict_last(t + (size_t)id4.x * 256 + lane * 32);
    V32 v1 = ldg256_evict_last(t + (size_t)id4.y * 256 + lane * 32);
    V32 v2 = ldg256_evict_last(t + (size_t)id4.z * 256 + lane * 32);
    V32 v3 = ldg256_evict_last(t + (size_t)id4.w * 256 + lane * 32);

    // out row r, chunk lane -> float4 index = lane*2
    float4* o = out + (size_t)row0 * F4_PER_ROW + lane * 2;
    stcs32(o + 0 * F4_PER_ROW, v0);
    stcs32(o + 1 * F4_PER_ROW, v1);
    stcs32(o + 2 * F4_PER_ROW, v2);
    stcs32(o + 3 * F4_PER_ROW, v3);
}

extern "C" void kernel_launch(void* const* d_in, const int* in_sizes, int n_in,
                              void* d_out, int out_size)
{
    const int*  ids   = (const int*)d_in[0];
    const char* table = (const char*)d_in[1];
    float4*     out   = (float4*)d_out;

    const int groups        = ROWS / ROWS_PER_GRP;          // 204800
    const int total_threads = groups * THR_PER_ROW;         // 1,638,400
    const int block = 256;
    const int grid  = (total_threads + block - 1) / block;  // 6400

    embed_gather_kernel<<<grid, block>>>(ids, table, out);
}